// round 1
// baseline (speedup 1.0000x reference)
#include <cuda_runtime.h>
#include <cstdint>

#define N_NODES 50000
#define FEAT 128
#define NRELS 4

// Scratch (static __device__ — no allocation allowed)
__device__ float g_A[(size_t)NRELS * N_NODES * FEAT];   // per-relation aggregated src features
__device__ float g_W[NRELS * FEAT * FEAT];              // composed per-relation weights

// ---------------------------------------------------------------------------
// W[r] = w_comp[r,0] * weight[0] + w_comp[r,1] * weight[1]
// ---------------------------------------------------------------------------
__global__ void compute_w_kernel(const float* __restrict__ weight,
                                 const float* __restrict__ w_comp) {
    int idx = blockIdx.x * blockDim.x + threadIdx.x;  // 4 * 16384 total
    int r = idx >> 14;
    int rest = idx & 16383;
    g_W[idx] = w_comp[r * 2 + 0] * weight[rest]
             + w_comp[r * 2 + 1] * weight[16384 + rest];
}

// ---------------------------------------------------------------------------
// Scatter: one warp per edge. Gather x[src] (float4/lane = full 128-d row per
// warp), vectorized reduction into A_r[dst].
// ---------------------------------------------------------------------------
__global__ void scatter_kernel(const float* __restrict__ x,
                               const int* __restrict__ src,
                               const int* __restrict__ dst,
                               float* __restrict__ Ar, int nE) {
    int e = blockIdx.x * 8 + (threadIdx.x >> 5);
    if (e >= nE) return;
    int lane = threadIdx.x & 31;
    int s = __ldg(src + e);
    int d = __ldg(dst + e);
    float4 v = *reinterpret_cast<const float4*>(x + (size_t)s * FEAT + lane * 4);
    float* p = Ar + (size_t)d * FEAT + lane * 4;
    asm volatile("red.global.add.v4.f32 [%0], {%1,%2,%3,%4};"
                 :: "l"(p), "f"(v.x), "f"(v.y), "f"(v.z), "f"(v.w) : "memory");
}

// ---------------------------------------------------------------------------
// GEMM + epilogue:
//   out[t] = A[t] @ W[t] + A[t+2] @ W[t+2] + bias      (t = dst node type)
// Block: 256 threads, 64 rows x 128 cols. W tile (64KB) + A tile (32KB) smem.
// Inner product uses packed fma.rn.f32x2 (2 fp32 FMA / instr) with column-pair
// accumulators: the 128-bit LDS of W gives both packed pairs for free.
// ---------------------------------------------------------------------------
__global__ void __launch_bounds__(256, 2)
gemm_kernel(const float* __restrict__ bias, float* __restrict__ out) {
    extern __shared__ float sm[];
    float* ws = sm;                 // [128][128]
    float* as = sm + FEAT * FEAT;   // [64][128]

    const int t = blockIdx.y;               // dst node type
    const int row0 = blockIdx.x * 64;
    const int warp = threadIdx.x >> 5;
    const int lane = threadIdx.x & 31;

    unsigned long long acc[8][2];           // 8 rows x 4 cols, packed f32x2
    #pragma unroll
    for (int r = 0; r < 8; r++) { acc[r][0] = 0ull; acc[r][1] = 0ull; }

    #pragma unroll
    for (int p = 0; p < 2; p++) {
        const int rel = t + p * 2;          // t=0 -> rels {0,2}; t=1 -> {1,3}

        // stage W[rel] (16384 floats) and A tile (64x128, zero-padded) in smem
        const float4* W4 = reinterpret_cast<const float4*>(g_W + rel * FEAT * FEAT);
        float4* ws4 = reinterpret_cast<float4*>(ws);
        for (int i = threadIdx.x; i < FEAT * FEAT / 4; i += 256) ws4[i] = W4[i];

        const float4* A4 = reinterpret_cast<const float4*>(g_A + (size_t)rel * N_NODES * FEAT);
        float4* as4 = reinterpret_cast<float4*>(as);
        for (int i = threadIdx.x; i < 64 * FEAT / 4; i += 256) {
            int row = i >> 5;
            int g = row0 + row;
            float4 v = make_float4(0.f, 0.f, 0.f, 0.f);
            if (g < N_NODES) v = A4[(size_t)g * 32 + (i & 31)];
            as4[i] = v;
        }
        __syncthreads();

        const ulonglong2* wsd = reinterpret_cast<const ulonglong2*>(ws);
        const float* asw = as + warp * 8 * FEAT;

        #pragma unroll 8
        for (int k = 0; k < FEAT; k++) {
            ulonglong2 wv = wsd[k * 32 + lane];   // cols [4*lane .. 4*lane+3] packed
            #pragma unroll
            for (int r = 0; r < 8; r++) {
                float x = asw[r * FEAT + k];      // broadcast LDS
                unsigned long long xx;
                asm("mov.b64 %0, {%1, %1};" : "=l"(xx) : "f"(x));
                asm("fma.rn.f32x2 %0, %1, %2, %0;" : "+l"(acc[r][0]) : "l"(xx), "l"(wv.x));
                asm("fma.rn.f32x2 %0, %1, %2, %0;" : "+l"(acc[r][1]) : "l"(xx), "l"(wv.y));
            }
        }
        __syncthreads();
    }

    // epilogue: unpack, add bias, store
    float4 b4 = reinterpret_cast<const float4*>(bias)[lane];
    #pragma unroll
    for (int r = 0; r < 8; r++) {
        int g = row0 + warp * 8 + r;
        if (g < N_NODES) {
            float f0, f1, f2, f3;
            asm("mov.b64 {%0, %1}, %2;" : "=f"(f0), "=f"(f1) : "l"(acc[r][0]));
            asm("mov.b64 {%0, %1}, %2;" : "=f"(f2), "=f"(f3) : "l"(acc[r][1]));
            float4 o;
            o.x = f0 + b4.x; o.y = f1 + b4.y; o.z = f2 + b4.z; o.w = f3 + b4.w;
            reinterpret_cast<float4*>(out)[((size_t)t * N_NODES + g) * 32 + lane] = o;
        }
    }
}

// ---------------------------------------------------------------------------
extern "C" void kernel_launch(void* const* d_in, const int* in_sizes, int n_in,
                              void* d_out, int out_size) {
    const float* x0     = (const float*)d_in[0];
    const float* x1     = (const float*)d_in[1];
    const float* weight = (const float*)d_in[2];
    const float* w_comp = (const float*)d_in[3];
    const float* bias   = (const float*)d_in[4];
    const int* src0 = (const int*)d_in[5];  const int* dst0 = (const int*)d_in[6];
    const int* src1 = (const int*)d_in[7];  const int* dst1 = (const int*)d_in[8];
    const int* src2 = (const int*)d_in[9];  const int* dst2 = (const int*)d_in[10];
    const int* src3 = (const int*)d_in[11]; const int* dst3 = (const int*)d_in[12];
    float* out = (float*)d_out;

    void* aptr = nullptr;
    cudaGetSymbolAddress(&aptr, g_A);
    float* A = (float*)aptr;

    // zero accumulators (must happen every call — graph replays)
    cudaMemsetAsync(aptr, 0, sizeof(float) * (size_t)NRELS * N_NODES * FEAT, 0);

    // compose per-relation weights
    compute_w_kernel<<<256, 256>>>(weight, w_comp);

    // per-relation scatter-add of raw src features
    const size_t NF = (size_t)N_NODES * FEAT;
    int E = in_sizes[5];
    int blk = (E + 7) / 8;
    scatter_kernel<<<blk, 256>>>(x0, src0, dst0, A + 0 * NF, E);
    E = in_sizes[7];  blk = (E + 7) / 8;
    scatter_kernel<<<blk, 256>>>(x0, src1, dst1, A + 1 * NF, E);
    E = in_sizes[9];  blk = (E + 7) / 8;
    scatter_kernel<<<blk, 256>>>(x1, src2, dst2, A + 2 * NF, E);
    E = in_sizes[11]; blk = (E + 7) / 8;
    scatter_kernel<<<blk, 256>>>(x1, src3, dst3, A + 3 * NF, E);

    // fused GEMM (two relations per dst type) + bias
    const int smem = (FEAT * FEAT + 64 * FEAT) * sizeof(float);  // 96 KB
    cudaFuncSetAttribute(gemm_kernel, cudaFuncAttributeMaxDynamicSharedMemorySize, smem);
    gemm_kernel<<<dim3((N_NODES + 63) / 64, 2), 256, smem>>>(bias, out);
}

// round 6
// speedup vs baseline: 1.2308x; 1.2308x over previous
#include <cuda_runtime.h>
#include <cuda_bf16.h>
#include <cstdint>

#define N_NODES 50000
#define FEAT 128
#define NRELS 4
#define NF ((size_t)N_NODES * FEAT)

// Scratch (static __device__ — no allocation allowed)
__device__ float g_A[(size_t)NRELS * N_NODES * FEAT];       // per-relation aggregated src feats
__device__ unsigned short g_Wb[NRELS * FEAT * FEAT];        // composed W^T [r][n][k], bf16 big
__device__ unsigned short g_Ws[NRELS * FEAT * FEAT];        // composed W^T [r][n][k], bf16 small

// ---------------------------------------------------------------------------
// helpers
// ---------------------------------------------------------------------------
__device__ __forceinline__ uint32_t smem_u32(const void* p) {
    uint32_t a;
    asm("{ .reg .u64 t; cvta.to.shared.u64 t, %1; cvt.u32.u64 %0, t; }" : "=r"(a) : "l"(p));
    return a;
}
__device__ __forceinline__ unsigned short f2bf(float x) {
    return __bfloat16_as_ushort(__float2bfloat16_rn(x));
}
__device__ __forceinline__ float bf2f(unsigned short u) {
    return __uint_as_float(((uint32_t)u) << 16);
}
__device__ __forceinline__ void ldsm4(uint32_t* r, uint32_t addr) {
    asm volatile("ldmatrix.sync.aligned.m8n8.x4.shared.b16 {%0,%1,%2,%3}, [%4];"
                 : "=r"(r[0]), "=r"(r[1]), "=r"(r[2]), "=r"(r[3]) : "r"(addr));
}
__device__ __forceinline__ void mma_bf16(float* d, const uint32_t* a, uint32_t b0, uint32_t b1) {
    asm volatile(
        "mma.sync.aligned.m16n8k16.row.col.f32.bf16.bf16.f32 "
        "{%0,%1,%2,%3}, {%4,%5,%6,%7}, {%8,%9}, {%0,%1,%2,%3};"
        : "+f"(d[0]), "+f"(d[1]), "+f"(d[2]), "+f"(d[3])
        : "r"(a[0]), "r"(a[1]), "r"(a[2]), "r"(a[3]), "r"(b0), "r"(b1));
}
#define SWZ(off) ((off) ^ (((off) >> 3) & 0x70))

// ---------------------------------------------------------------------------
// W precompute: W^T[r][n][k] composed from bases, split to bf16 big + small
// ---------------------------------------------------------------------------
__global__ void compute_w_kernel(const float* __restrict__ weight,
                                 const float* __restrict__ w_comp) {
    int idx = blockIdx.x * blockDim.x + threadIdx.x;   // 4 * 16384, idx = r*16384 + n*128 + k
    int r = idx >> 14;
    int k = idx & 127;
    int n = (idx >> 7) & 127;
    float w = w_comp[r * 2 + 0] * weight[k * 128 + n]
            + w_comp[r * 2 + 1] * weight[16384 + k * 128 + n];
    unsigned short big = f2bf(w);
    g_Wb[idx] = big;
    g_Ws[idx] = f2bf(w - bf2f(big));
}

// ---------------------------------------------------------------------------
// Scatter: one warp per edge, vectorized red.global.add (round-1 proven)
// ---------------------------------------------------------------------------
__global__ void scatter_kernel(const float* __restrict__ x,
                               const int* __restrict__ src,
                               const int* __restrict__ dst,
                               float* __restrict__ Ar, int nE) {
    int e = blockIdx.x * 8 + (threadIdx.x >> 5);
    if (e >= nE) return;
    int lane = threadIdx.x & 31;
    int s = __ldg(src + e);
    int d = __ldg(dst + e);
    float4 v = *reinterpret_cast<const float4*>(x + (size_t)s * FEAT + lane * 4);
    float* p = Ar + (size_t)d * FEAT + lane * 4;
    asm volatile("red.global.add.v4.f32 [%0], {%1,%2,%3,%4};"
                 :: "l"(p), "f"(v.x), "f"(v.y), "f"(v.z), "f"(v.w) : "memory");
}

// ---------------------------------------------------------------------------
// bf16 mma.sync GEMM with big/small compensation (3 products).
// CTA tile M=128 x N=128, K=128 resident. out[t] = sum_rel A_rel @ W_rel^T + bias.
// SMEM: 4 tiles (Ab/As/Bb/Bs), each [2 kchunks][128 rows][64 cols] bf16,
// rows of 128B with SW128 swizzle -> conflict-free ldmatrix.
// Warps: 4 (M) x 2 (N); warp tile 32x64.
// ---------------------------------------------------------------------------
#define SM_AB 0
#define SM_AS 32768
#define SM_BB 65536
#define SM_BS 98304
#define SMEM_BYTES 131072

__global__ void __launch_bounds__(256, 1)
gemm_kernel(const float* __restrict__ bias, float* __restrict__ out) {
    extern __shared__ char smem_raw[];
    const uint32_t base = smem_u32(smem_raw);

    const int t = blockIdx.y;
    const int row0 = blockIdx.x * 128;
    const int tid = threadIdx.x;
    const int lane = tid & 31;
    const int warp = tid >> 5;
    const int m0 = (warp & 3) * 32;      // warp row offset in tile
    const int n0 = (warp >> 2) * 64;     // warp col offset in tile

    float acc[2][8][4];
    #pragma unroll
    for (int mf = 0; mf < 2; mf++)
        #pragma unroll
        for (int nf = 0; nf < 8; nf++)
            #pragma unroll
            for (int i = 0; i < 4; i++) acc[mf][nf][i] = 0.f;

    // ldmatrix lane addressing (8x8 tile rows), hoisted
    const int lrow = (lane & 7) + 8 * ((lane >> 3) & 1);
    const int lkb  = (lane >> 4) * 8;

    for (int p = 0; p < 2; p++) {
        const int rel = t + p * 2;
        const float* Abase = g_A + (size_t)rel * NF;
        const unsigned short* WBb = g_Wb + rel * FEAT * FEAT;
        const unsigned short* WSb = g_Ws + rel * FEAT * FEAT;

        // ---- stage A (fp32 -> bf16 big/small) ----
        #pragma unroll
        for (int j = 0; j < 8; j++) {
            int i = tid + j * 256;            // 2048 groups of 8 floats
            int row = i >> 4;
            int kq = i & 15;                  // 8-float group index
            int g = row0 + row;
            float4 v0 = make_float4(0.f, 0.f, 0.f, 0.f), v1 = v0;
            if (g < N_NODES) {
                const float4* src = reinterpret_cast<const float4*>(Abase + (size_t)g * FEAT + kq * 8);
                v0 = __ldg(src); v1 = __ldg(src + 1);
            }
            float f[8] = {v0.x, v0.y, v0.z, v0.w, v1.x, v1.y, v1.z, v1.w};
            uint32_t B[4], S[4];
            #pragma unroll
            for (int q = 0; q < 4; q++) {
                unsigned short b0 = f2bf(f[2 * q]);
                unsigned short b1 = f2bf(f[2 * q + 1]);
                unsigned short s0 = f2bf(f[2 * q] - bf2f(b0));
                unsigned short s1 = f2bf(f[2 * q + 1] - bf2f(b1));
                B[q] = ((uint32_t)b1 << 16) | b0;
                S[q] = ((uint32_t)s1 << 16) | s0;
            }
            int kchunk = kq >> 3;
            int kk = kq & 7;
            uint32_t off = (uint32_t)(row * 128 + kk * 16);
            uint32_t sw = SWZ(off) + kchunk * 16384;
            asm volatile("st.shared.v4.b32 [%0], {%1,%2,%3,%4};"
                         :: "r"(base + SM_AB + sw), "r"(B[0]), "r"(B[1]), "r"(B[2]), "r"(B[3]) : "memory");
            asm volatile("st.shared.v4.b32 [%0], {%1,%2,%3,%4};"
                         :: "r"(base + SM_AS + sw), "r"(S[0]), "r"(S[1]), "r"(S[2]), "r"(S[3]) : "memory");
        }
        // ---- stage W^T (pre-split bf16) ----
        #pragma unroll
        for (int j = 0; j < 8; j++) {
            int i = tid + j * 256;
            int n = i >> 4;
            int kq = i & 15;
            uint4 vb = __ldg(reinterpret_cast<const uint4*>(WBb + n * FEAT + kq * 8));
            uint4 vs = __ldg(reinterpret_cast<const uint4*>(WSb + n * FEAT + kq * 8));
            int kchunk = kq >> 3;
            int kk = kq & 7;
            uint32_t off = (uint32_t)(n * 128 + kk * 16);
            uint32_t sw = SWZ(off) + kchunk * 16384;
            asm volatile("st.shared.v4.b32 [%0], {%1,%2,%3,%4};"
                         :: "r"(base + SM_BB + sw), "r"(vb.x), "r"(vb.y), "r"(vb.z), "r"(vb.w) : "memory");
            asm volatile("st.shared.v4.b32 [%0], {%1,%2,%3,%4};"
                         :: "r"(base + SM_BS + sw), "r"(vs.x), "r"(vs.y), "r"(vs.z), "r"(vs.w) : "memory");
        }
        __syncthreads();

        // ---- compute: 8 k16 steps ----
        #pragma unroll
        for (int ks = 0; ks < 8; ks++) {
            const int kchunk = ks >> 2;
            const int kk0 = (ks & 3) * 16;
            const uint32_t cbase = kchunk * 16384;

            uint32_t aB[2][4], aS[2][4];
            #pragma unroll
            for (int mf = 0; mf < 2; mf++) {
                uint32_t off = (uint32_t)((m0 + mf * 16 + lrow) * 128 + (kk0 + lkb) * 2);
                uint32_t sw = SWZ(off) + cbase;
                ldsm4(aB[mf], base + SM_AB + sw);
                ldsm4(aS[mf], base + SM_AS + sw);
            }
            uint32_t bB[4][4], bS[4][4];
            #pragma unroll
            for (int ng = 0; ng < 4; ng++) {
                uint32_t off = (uint32_t)((n0 + ng * 16 + lrow) * 128 + (kk0 + lkb) * 2);
                uint32_t sw = SWZ(off) + cbase;
                ldsm4(bB[ng], base + SM_BB + sw);
                ldsm4(bS[ng], base + SM_BS + sw);
            }
            #pragma unroll
            for (int mf = 0; mf < 2; mf++) {
                #pragma unroll
                for (int nf = 0; nf < 8; nf++) {
                    int ng = nf >> 1, sel = nf & 1;
                    mma_bf16(acc[mf][nf], aB[mf], bB[ng][sel], bB[ng][sel + 2]);
                    mma_bf16(acc[mf][nf], aB[mf], bS[ng][sel], bS[ng][sel + 2]);
                    mma_bf16(acc[mf][nf], aS[mf], bB[ng][sel], bB[ng][sel + 2]);
                }
            }
        }
        __syncthreads();
    }

    // ---- epilogue: + bias, store fp32 ----
    #pragma unroll
    for (int nf = 0; nf < 8; nf++) {
        int col = n0 + nf * 8 + 2 * (lane & 3);
        float bx = __ldg(bias + col);
        float by = __ldg(bias + col + 1);
        #pragma unroll
        for (int mf = 0; mf < 2; mf++) {
            int g = row0 + m0 + mf * 16 + (lane >> 2);
            const float* a4 = acc[mf][nf];
            if (g < N_NODES) {
                float2 o = make_float2(a4[0] + bx, a4[1] + by);
                *reinterpret_cast<float2*>(out + ((size_t)t * N_NODES + g) * FEAT + col) = o;
            }
            if (g + 8 < N_NODES) {
                float2 o = make_float2(a4[2] + bx, a4[3] + by);
                *reinterpret_cast<float2*>(out + ((size_t)t * N_NODES + g + 8) * FEAT + col) = o;
            }
        }
    }
}

// ---------------------------------------------------------------------------
extern "C" void kernel_launch(void* const* d_in, const int* in_sizes, int n_in,
                              void* d_out, int out_size) {
    const float* x0     = (const float*)d_in[0];
    const float* x1     = (const float*)d_in[1];
    const float* weight = (const float*)d_in[2];
    const float* w_comp = (const float*)d_in[3];
    const float* bias   = (const float*)d_in[4];
    const int* src0 = (const int*)d_in[5];  const int* dst0 = (const int*)d_in[6];
    const int* src1 = (const int*)d_in[7];  const int* dst1 = (const int*)d_in[8];
    const int* src2 = (const int*)d_in[9];  const int* dst2 = (const int*)d_in[10];
    const int* src3 = (const int*)d_in[11]; const int* dst3 = (const int*)d_in[12];
    float* out = (float*)d_out;

    void* aptr = nullptr;
    cudaGetSymbolAddress(&aptr, g_A);
    float* A = (float*)aptr;

    cudaMemsetAsync(aptr, 0, sizeof(float) * NRELS * NF, 0);
    compute_w_kernel<<<256, 256>>>(weight, w_comp);

    int E = in_sizes[5];
    scatter_kernel<<<(E + 7) / 8, 256>>>(x0, src0, dst0, A + 0 * NF, E);
    E = in_sizes[7];
    scatter_kernel<<<(E + 7) / 8, 256>>>(x0, src1, dst1, A + 1 * NF, E);
    E = in_sizes[9];
    scatter_kernel<<<(E + 7) / 8, 256>>>(x1, src2, dst2, A + 2 * NF, E);
    E = in_sizes[11];
    scatter_kernel<<<(E + 7) / 8, 256>>>(x1, src3, dst3, A + 3 * NF, E);

    cudaFuncSetAttribute(gemm_kernel, cudaFuncAttributeMaxDynamicSharedMemorySize, SMEM_BYTES);
    gemm_kernel<<<dim3((N_NODES + 127) / 128, 2), 256, SMEM_BYTES>>>(bias, out);
}

// round 7
// speedup vs baseline: 1.3757x; 1.1177x over previous
#include <cuda_runtime.h>
#include <cuda_bf16.h>
#include <cstdint>

#define N_NODES 50000
#define FEAT 128
#define NRELS 4
#define NF ((size_t)N_NODES * FEAT)

// Scratch (static __device__ — no allocation allowed)
__device__ float g_A[(size_t)NRELS * N_NODES * FEAT];       // per-relation aggregated src feats
__device__ unsigned short g_Wb[NRELS * FEAT * FEAT];        // composed W^T [r][n][k], bf16 big
__device__ unsigned short g_Ws[NRELS * FEAT * FEAT];        // composed W^T [r][n][k], bf16 small

// ---------------------------------------------------------------------------
// helpers
// ---------------------------------------------------------------------------
__device__ __forceinline__ uint32_t smem_u32(const void* p) {
    uint32_t a;
    asm("{ .reg .u64 t; cvta.to.shared.u64 t, %1; cvt.u32.u64 %0, t; }" : "=r"(a) : "l"(p));
    return a;
}
__device__ __forceinline__ unsigned short f2bf(float x) {
    return __bfloat16_as_ushort(__float2bfloat16_rn(x));
}
__device__ __forceinline__ float bf2f(unsigned short u) {
    return __uint_as_float(((uint32_t)u) << 16);
}
__device__ __forceinline__ void ldsm4(uint32_t* r, uint32_t addr) {
    asm volatile("ldmatrix.sync.aligned.m8n8.x4.shared.b16 {%0,%1,%2,%3}, [%4];"
                 : "=r"(r[0]), "=r"(r[1]), "=r"(r[2]), "=r"(r[3]) : "r"(addr));
}
__device__ __forceinline__ void mma_bf16(float* d, const uint32_t* a, uint32_t b0, uint32_t b1) {
    asm volatile(
        "mma.sync.aligned.m16n8k16.row.col.f32.bf16.bf16.f32 "
        "{%0,%1,%2,%3}, {%4,%5,%6,%7}, {%8,%9}, {%0,%1,%2,%3};"
        : "+f"(d[0]), "+f"(d[1]), "+f"(d[2]), "+f"(d[3])
        : "r"(a[0]), "r"(a[1]), "r"(a[2]), "r"(a[3]), "r"(b0), "r"(b1));
}
#define SWZ(off) ((off) ^ (((off) >> 3) & 0x70))

// ---------------------------------------------------------------------------
// W precompute: W^T[r][n][k] composed from bases, split to bf16 big + small
// ---------------------------------------------------------------------------
__global__ void compute_w_kernel(const float* __restrict__ weight,
                                 const float* __restrict__ w_comp) {
    int idx = blockIdx.x * blockDim.x + threadIdx.x;   // 4 * 16384, idx = r*16384 + n*128 + k
    int r = idx >> 14;
    int k = idx & 127;
    int n = (idx >> 7) & 127;
    float w = w_comp[r * 2 + 0] * weight[k * 128 + n]
            + w_comp[r * 2 + 1] * weight[16384 + k * 128 + n];
    unsigned short big = f2bf(w);
    g_Wb[idx] = big;
    g_Ws[idx] = f2bf(w - bf2f(big));
}

// ---------------------------------------------------------------------------
// Fused scatter: all 4 relations in one grid (round-robin by warp batch) so
// all four atomic regions + both x tables are in flight together. Each warp
// handles 4 edges, software-batched (all gathers issued, then all reductions)
// to raise MLP on this latency-bound loop.
// ---------------------------------------------------------------------------
__global__ void __launch_bounds__(256)
scatter4_kernel(const float* __restrict__ x0, const float* __restrict__ x1,
                const int* __restrict__ s0, const int* __restrict__ d0,
                const int* __restrict__ s1, const int* __restrict__ d1,
                const int* __restrict__ s2, const int* __restrict__ d2,
                const int* __restrict__ s3, const int* __restrict__ d3,
                float* __restrict__ A,
                int E0, int E1, int E2, int E3, int bmax) {
    int b = blockIdx.x * 8 + (threadIdx.x >> 5);   // warp batch id
    if (b >= bmax) return;
    int lane = threadIdx.x & 31;
    int rel = b & 3;
    int le0 = (b >> 2) * 4;

    const float* x; const int* sp; const int* dp; int E;
    if (rel == 0)      { x = x0; sp = s0; dp = d0; E = E0; }
    else if (rel == 1) { x = x0; sp = s1; dp = d1; E = E1; }
    else if (rel == 2) { x = x1; sp = s2; dp = d2; E = E2; }
    else               { x = x1; sp = s3; dp = d3; E = E3; }
    int cnt = E - le0;
    if (cnt <= 0) return;
    if (cnt > 4) cnt = 4;
    float* Ar = A + (size_t)rel * NF;

    int s[4], d[4];
    #pragma unroll
    for (int q = 0; q < 4; q++)
        if (q < cnt) { s[q] = __ldg(sp + le0 + q); d[q] = __ldg(dp + le0 + q); }
    float4 v[4];
    #pragma unroll
    for (int q = 0; q < 4; q++)
        if (q < cnt) v[q] = __ldg(reinterpret_cast<const float4*>(x + (size_t)s[q] * FEAT) + lane);
    #pragma unroll
    for (int q = 0; q < 4; q++)
        if (q < cnt) {
            float* p = Ar + (size_t)d[q] * FEAT + lane * 4;
            asm volatile("red.global.add.v4.f32 [%0], {%1,%2,%3,%4};"
                         :: "l"(p), "f"(v[q].x), "f"(v[q].y), "f"(v[q].z), "f"(v[q].w) : "memory");
        }
}

// ---------------------------------------------------------------------------
// bf16 mma.sync GEMM with big/small compensation (3 products).
// CTA tile M=128 x N=64 (blockIdx.z picks the N-half), K staged in 4 chunks
// of 64 (2 rels x 2 kchunks). smem/chunk = Ab/As 16KB each + Bb/Bs 8KB each
// = 48KB -> 2-3 CTAs/SM, so one CTA's staging overlaps another's MMAs.
// 8 warps as 4(M) x 2(N); warp tile 32x32, 32 acc regs.
// ---------------------------------------------------------------------------
#define SM_AB 0
#define SM_AS 16384
#define SM_BB 32768
#define SM_BS 40960
#define SMEM_BYTES 49152

__global__ void __launch_bounds__(256, 2)
gemm_kernel(const float* __restrict__ bias, float* __restrict__ out) {
    extern __shared__ char smem_raw[];
    const uint32_t base = smem_u32(smem_raw);

    const int t = blockIdx.y;
    const int row0 = blockIdx.x * 128;
    const int nb = blockIdx.z * 64;      // N-half base
    const int tid = threadIdx.x;
    const int lane = tid & 31;
    const int warp = tid >> 5;
    const int m0 = (warp & 3) * 32;      // warp row offset in tile
    const int n0 = (warp >> 2) * 32;     // warp col offset within 64-col half

    float acc[2][4][4];
    #pragma unroll
    for (int mf = 0; mf < 2; mf++)
        #pragma unroll
        for (int nf = 0; nf < 4; nf++)
            #pragma unroll
            for (int i = 0; i < 4; i++) acc[mf][nf][i] = 0.f;

    // ldmatrix lane addressing (8x8 tile rows), hoisted
    const int lrow = (lane & 7) + 8 * ((lane >> 3) & 1);
    const int lkb  = (lane >> 4) * 8;

    #pragma unroll 1
    for (int c = 0; c < 4; c++) {
        const int rel = t + (c >> 1) * 2;
        const int kc = c & 1;
        const float* Abase = g_A + (size_t)rel * NF;
        const unsigned short* WBb = g_Wb + rel * FEAT * FEAT;
        const unsigned short* WSb = g_Ws + rel * FEAT * FEAT;

        if (c) __syncthreads();          // previous compute done before restage

        // ---- stage A chunk (128 rows x 64 k), fp32 -> bf16 big/small ----
        #pragma unroll
        for (int j = 0; j < 4; j++) {
            int i = tid + j * 256;            // 1024 groups of 8 floats
            int row = i >> 3;
            int kq = i & 7;                   // 8-float group within chunk
            int g = row0 + row;
            float4 v0 = make_float4(0.f, 0.f, 0.f, 0.f), v1 = v0;
            if (g < N_NODES) {
                const float4* src = reinterpret_cast<const float4*>(Abase + (size_t)g * FEAT + kc * 64 + kq * 8);
                v0 = __ldg(src); v1 = __ldg(src + 1);
            }
            float f[8] = {v0.x, v0.y, v0.z, v0.w, v1.x, v1.y, v1.z, v1.w};
            uint32_t B[4], S[4];
            #pragma unroll
            for (int q = 0; q < 4; q++) {
                unsigned short b0 = f2bf(f[2 * q]);
                unsigned short b1 = f2bf(f[2 * q + 1]);
                unsigned short s0 = f2bf(f[2 * q] - bf2f(b0));
                unsigned short s1 = f2bf(f[2 * q + 1] - bf2f(b1));
                B[q] = ((uint32_t)b1 << 16) | b0;
                S[q] = ((uint32_t)s1 << 16) | s0;
            }
            uint32_t off = (uint32_t)(row * 128 + kq * 16);
            uint32_t sw = SWZ(off);
            asm volatile("st.shared.v4.b32 [%0], {%1,%2,%3,%4};"
                         :: "r"(base + SM_AB + sw), "r"(B[0]), "r"(B[1]), "r"(B[2]), "r"(B[3]) : "memory");
            asm volatile("st.shared.v4.b32 [%0], {%1,%2,%3,%4};"
                         :: "r"(base + SM_AS + sw), "r"(S[0]), "r"(S[1]), "r"(S[2]), "r"(S[3]) : "memory");
        }
        // ---- stage W^T chunk (64 n-rows x 64 k), pre-split bf16 ----
        #pragma unroll
        for (int j = 0; j < 2; j++) {
            int i = tid + j * 256;            // 512 groups
            int n = i >> 3;                   // 0..63
            int kq = i & 7;
            uint4 vb = __ldg(reinterpret_cast<const uint4*>(WBb + (nb + n) * FEAT + kc * 64 + kq * 8));
            uint4 vs = __ldg(reinterpret_cast<const uint4*>(WSb + (nb + n) * FEAT + kc * 64 + kq * 8));
            uint32_t off = (uint32_t)(n * 128 + kq * 16);
            uint32_t sw = SWZ(off);
            asm volatile("st.shared.v4.b32 [%0], {%1,%2,%3,%4};"
                         :: "r"(base + SM_BB + sw), "r"(vb.x), "r"(vb.y), "r"(vb.z), "r"(vb.w) : "memory");
            asm volatile("st.shared.v4.b32 [%0], {%1,%2,%3,%4};"
                         :: "r"(base + SM_BS + sw), "r"(vs.x), "r"(vs.y), "r"(vs.z), "r"(vs.w) : "memory");
        }
        __syncthreads();

        // ---- compute: 4 k16 steps ----
        #pragma unroll
        for (int ks = 0; ks < 4; ks++) {
            const int kk0 = ks * 16;

            uint32_t aB[2][4], aS[2][4];
            #pragma unroll
            for (int mf = 0; mf < 2; mf++) {
                uint32_t off = (uint32_t)((m0 + mf * 16 + lrow) * 128 + (kk0 + lkb) * 2);
                uint32_t sw = SWZ(off);
                ldsm4(aB[mf], base + SM_AB + sw);
                ldsm4(aS[mf], base + SM_AS + sw);
            }
            uint32_t bB[2][4], bS[2][4];
            #pragma unroll
            for (int ng = 0; ng < 2; ng++) {
                uint32_t off = (uint32_t)((n0 + ng * 16 + lrow) * 128 + (kk0 + lkb) * 2);
                uint32_t sw = SWZ(off);
                ldsm4(bB[ng], base + SM_BB + sw);
                ldsm4(bS[ng], base + SM_BS + sw);
            }
            #pragma unroll
            for (int mf = 0; mf < 2; mf++) {
                #pragma unroll
                for (int nf = 0; nf < 4; nf++) {
                    int ng = nf >> 1, sel = nf & 1;
                    mma_bf16(acc[mf][nf], aB[mf], bB[ng][sel], bB[ng][sel + 2]);
                    mma_bf16(acc[mf][nf], aB[mf], bS[ng][sel], bS[ng][sel + 2]);
                    mma_bf16(acc[mf][nf], aS[mf], bB[ng][sel], bB[ng][sel + 2]);
                }
            }
        }
    }

    // ---- epilogue: + bias, store fp32 ----
    #pragma unroll
    for (int nf = 0; nf < 4; nf++) {
        int col = nb + n0 + nf * 8 + 2 * (lane & 3);
        float bx = __ldg(bias + col);
        float by = __ldg(bias + col + 1);
        #pragma unroll
        for (int mf = 0; mf < 2; mf++) {
            int g = row0 + m0 + mf * 16 + (lane >> 2);
            const float* a4 = acc[mf][nf];
            if (g < N_NODES) {
                float2 o = make_float2(a4[0] + bx, a4[1] + by);
                *reinterpret_cast<float2*>(out + ((size_t)t * N_NODES + g) * FEAT + col) = o;
            }
            if (g + 8 < N_NODES) {
                float2 o = make_float2(a4[2] + bx, a4[3] + by);
                *reinterpret_cast<float2*>(out + ((size_t)t * N_NODES + g + 8) * FEAT + col) = o;
            }
        }
    }
}

// ---------------------------------------------------------------------------
extern "C" void kernel_launch(void* const* d_in, const int* in_sizes, int n_in,
                              void* d_out, int out_size) {
    const float* x0     = (const float*)d_in[0];
    const float* x1     = (const float*)d_in[1];
    const float* weight = (const float*)d_in[2];
    const float* w_comp = (const float*)d_in[3];
    const float* bias   = (const float*)d_in[4];
    const int* src0 = (const int*)d_in[5];  const int* dst0 = (const int*)d_in[6];
    const int* src1 = (const int*)d_in[7];  const int* dst1 = (const int*)d_in[8];
    const int* src2 = (const int*)d_in[9];  const int* dst2 = (const int*)d_in[10];
    const int* src3 = (const int*)d_in[11]; const int* dst3 = (const int*)d_in[12];
    float* out = (float*)d_out;

    void* aptr = nullptr;
    cudaGetSymbolAddress(&aptr, g_A);
    float* A = (float*)aptr;

    cudaMemsetAsync(aptr, 0, sizeof(float) * NRELS * NF, 0);
    compute_w_kernel<<<256, 256>>>(weight, w_comp);

    int E0 = in_sizes[5], E1 = in_sizes[7], E2 = in_sizes[9], E3 = in_sizes[11];
    int Emax = E0;
    if (E1 > Emax) Emax = E1;
    if (E2 > Emax) Emax = E2;
    if (E3 > Emax) Emax = E3;
    int bpr = (Emax + 3) / 4;          // warp batches per relation
    int bmax = bpr * 4;
    scatter4_kernel<<<(bmax + 7) / 8, 256>>>(x0, x1, src0, dst0, src1, dst1,
                                             src2, dst2, src3, dst3, A,
                                             E0, E1, E2, E3, bmax);

    cudaFuncSetAttribute(gemm_kernel, cudaFuncAttributeMaxDynamicSharedMemorySize, SMEM_BYTES);
    gemm_kernel<<<dim3((N_NODES + 127) / 128, 2, 2), 256, SMEM_BYTES>>>(bias, out);
}

// round 8
// speedup vs baseline: 1.4415x; 1.0479x over previous
#include <cuda_runtime.h>
#include <cuda_bf16.h>
#include <cstdint>

#define N_NODES 50000
#define FEAT 128
#define NRELS 4
#define NF ((size_t)N_NODES * FEAT)

// Scratch (static __device__ — no allocation allowed)
__device__ float g_A[(size_t)NRELS * N_NODES * FEAT];       // per-relation aggregated src feats
__device__ unsigned short g_Wb[NRELS * FEAT * FEAT];        // composed W^T [r][n][k], bf16 big
__device__ unsigned short g_Ws[NRELS * FEAT * FEAT];        // composed W^T [r][n][k], bf16 small

// ---------------------------------------------------------------------------
// helpers
// ---------------------------------------------------------------------------
__device__ __forceinline__ uint32_t smem_u32(const void* p) {
    uint32_t a;
    asm("{ .reg .u64 t; cvta.to.shared.u64 t, %1; cvt.u32.u64 %0, t; }" : "=r"(a) : "l"(p));
    return a;
}
__device__ __forceinline__ unsigned short f2bf(float x) {
    return __bfloat16_as_ushort(__float2bfloat16_rn(x));
}
__device__ __forceinline__ float bf2f(unsigned short u) {
    return __uint_as_float(((uint32_t)u) << 16);
}
__device__ __forceinline__ void ldsm4(uint32_t* r, uint32_t addr) {
    asm volatile("ldmatrix.sync.aligned.m8n8.x4.shared.b16 {%0,%1,%2,%3}, [%4];"
                 : "=r"(r[0]), "=r"(r[1]), "=r"(r[2]), "=r"(r[3]) : "r"(addr));
}
__device__ __forceinline__ void mma_bf16(float* d, const uint32_t* a, uint32_t b0, uint32_t b1) {
    asm volatile(
        "mma.sync.aligned.m16n8k16.row.col.f32.bf16.bf16.f32 "
        "{%0,%1,%2,%3}, {%4,%5,%6,%7}, {%8,%9}, {%0,%1,%2,%3};"
        : "+f"(d[0]), "+f"(d[1]), "+f"(d[2]), "+f"(d[3])
        : "r"(a[0]), "r"(a[1]), "r"(a[2]), "r"(a[3]), "r"(b0), "r"(b1));
}
__device__ __forceinline__ void cp_async16(uint32_t smem_dst, const void* gsrc) {
    asm volatile("cp.async.cg.shared.global [%0], [%1], 16;"
                 :: "r"(smem_dst), "l"(gsrc) : "memory");
}
#define SWZ(off) ((off) ^ (((off) >> 3) & 0x70))

// ---------------------------------------------------------------------------
// W precompute: W^T[r][n][k] composed from bases, split to bf16 big + small
// ---------------------------------------------------------------------------
__global__ void compute_w_kernel(const float* __restrict__ weight,
                                 const float* __restrict__ w_comp) {
    int idx = blockIdx.x * blockDim.x + threadIdx.x;   // 4 * 16384, idx = r*16384 + n*128 + k
    int r = idx >> 14;
    int k = idx & 127;
    int n = (idx >> 7) & 127;
    float w = w_comp[r * 2 + 0] * weight[k * 128 + n]
            + w_comp[r * 2 + 1] * weight[16384 + k * 128 + n];
    unsigned short big = f2bf(w);
    g_Wb[idx] = big;
    g_Ws[idx] = f2bf(w - bf2f(big));
}

// ---------------------------------------------------------------------------
// Fused scatter: one launch, relation chosen per BLOCK (locality: each block
// touches one x table + one A region), blocks interleaved across relations.
// Each warp handles 4 edges software-batched (all gathers in flight before
// the reductions) for MLP on this latency-bound loop.
// ---------------------------------------------------------------------------
__global__ void __launch_bounds__(256)
scatter4_kernel(const float* __restrict__ x0, const float* __restrict__ x1,
                const int* __restrict__ s0, const int* __restrict__ d0,
                const int* __restrict__ s1, const int* __restrict__ d1,
                const int* __restrict__ s2, const int* __restrict__ d2,
                const int* __restrict__ s3, const int* __restrict__ d3,
                float* __restrict__ A,
                int E0, int E1, int E2, int E3) {
    int rel = blockIdx.x & 3;
    int e0 = (blockIdx.x >> 2) * 32 + (threadIdx.x >> 5) * 4;  // 32 edges per block
    int lane = threadIdx.x & 31;

    const float* x; const int* sp; const int* dp; int E;
    if (rel == 0)      { x = x0; sp = s0; dp = d0; E = E0; }
    else if (rel == 1) { x = x0; sp = s1; dp = d1; E = E1; }
    else if (rel == 2) { x = x1; sp = s2; dp = d2; E = E2; }
    else               { x = x1; sp = s3; dp = d3; E = E3; }
    int cnt = E - e0;
    if (cnt <= 0) return;
    if (cnt > 4) cnt = 4;
    float* Ar = A + (size_t)rel * NF;

    int s[4], d[4];
    #pragma unroll
    for (int q = 0; q < 4; q++)
        if (q < cnt) { s[q] = __ldg(sp + e0 + q); d[q] = __ldg(dp + e0 + q); }
    float4 v[4];
    #pragma unroll
    for (int q = 0; q < 4; q++)
        if (q < cnt) v[q] = __ldg(reinterpret_cast<const float4*>(x + (size_t)s[q] * FEAT) + lane);
    #pragma unroll
    for (int q = 0; q < 4; q++)
        if (q < cnt) {
            float* p = Ar + (size_t)d[q] * FEAT + lane * 4;
            asm volatile("red.global.add.v4.f32 [%0], {%1,%2,%3,%4};"
                         :: "l"(p), "f"(v[q].x), "f"(v[q].y), "f"(v[q].z), "f"(v[q].w) : "memory");
        }
}

// ---------------------------------------------------------------------------
// bf16 mma.sync GEMM with big/small compensation (3 products).
// CTA tile M=64 x N=128, K staged in 4 chunks of 64 (2 rels x 2 kchunks).
// A (the unique 100MB stream) is read exactly once; B (256KB unique, L2-hot)
// is the re-read quantity. smem/chunk = A 16KB + B 32KB = 48KB -> occ>=2.
// B staged via cp.async (raw bf16), overlapped with A's fp32->bf16 convert.
// 8 warps as 2(M) x 4(N); warp tile 32x32, 32 acc regs.
// ---------------------------------------------------------------------------
#define SM_AB 0
#define SM_AS 8192
#define SM_BB 16384
#define SM_BS 32768
#define SMEM_BYTES 49152

__global__ void __launch_bounds__(256, 2)
gemm_kernel(const float* __restrict__ bias, float* __restrict__ out) {
    extern __shared__ char smem_raw[];
    const uint32_t base = smem_u32(smem_raw);

    const int t = blockIdx.y;
    const int row0 = blockIdx.x * 64;
    const int tid = threadIdx.x;
    const int lane = tid & 31;
    const int warp = tid >> 5;
    const int m0 = (warp & 1) * 32;      // warp row offset in 64-row tile
    const int n0 = (warp >> 1) * 32;     // warp col offset in 128-col tile

    float acc[2][4][4];
    #pragma unroll
    for (int mf = 0; mf < 2; mf++)
        #pragma unroll
        for (int nf = 0; nf < 4; nf++)
            #pragma unroll
            for (int i = 0; i < 4; i++) acc[mf][nf][i] = 0.f;

    // ldmatrix lane addressing (8x8 tile rows), hoisted
    const int lrow = (lane & 7) + 8 * ((lane >> 3) & 1);
    const int lkb  = (lane >> 4) * 8;

    #pragma unroll 1
    for (int c = 0; c < 4; c++) {
        const int rel = t + (c >> 1) * 2;
        const int kc = c & 1;
        const float* Abase = g_A + (size_t)rel * NF;
        const unsigned short* WBb = g_Wb + rel * FEAT * FEAT;
        const unsigned short* WSb = g_Ws + rel * FEAT * FEAT;

        if (c) __syncthreads();          // previous compute done before restage

        // ---- B chunk via cp.async first (overlaps with A convert below) ----
        #pragma unroll
        for (int j = 0; j < 4; j++) {
            int i = tid + j * 256;            // 1024 groups of 8 bf16
            int n = i >> 3;                   // 0..127
            int kq = i & 7;
            uint32_t sw = SWZ((uint32_t)(n * 128 + kq * 16));
            cp_async16(base + SM_BB + sw, WBb + n * FEAT + kc * 64 + kq * 8);
            cp_async16(base + SM_BS + sw, WSb + n * FEAT + kc * 64 + kq * 8);
        }
        asm volatile("cp.async.commit_group;" ::: "memory");

        // ---- stage A chunk (64 rows x 64 k), fp32 -> bf16 big/small ----
        #pragma unroll
        for (int j = 0; j < 2; j++) {
            int i = tid + j * 256;            // 512 groups of 8 floats
            int row = i >> 3;                 // 0..63
            int kq = i & 7;
            int g = row0 + row;
            float4 v0 = make_float4(0.f, 0.f, 0.f, 0.f), v1 = v0;
            if (g < N_NODES) {
                const float4* src = reinterpret_cast<const float4*>(Abase + (size_t)g * FEAT + kc * 64 + kq * 8);
                v0 = __ldg(src); v1 = __ldg(src + 1);
            }
            float f[8] = {v0.x, v0.y, v0.z, v0.w, v1.x, v1.y, v1.z, v1.w};
            uint32_t B[4], S[4];
            #pragma unroll
            for (int q = 0; q < 4; q++) {
                unsigned short b0 = f2bf(f[2 * q]);
                unsigned short b1 = f2bf(f[2 * q + 1]);
                unsigned short s0 = f2bf(f[2 * q] - bf2f(b0));
                unsigned short s1 = f2bf(f[2 * q + 1] - bf2f(b1));
                B[q] = ((uint32_t)b1 << 16) | b0;
                S[q] = ((uint32_t)s1 << 16) | s0;
            }
            uint32_t sw = SWZ((uint32_t)(row * 128 + kq * 16));
            asm volatile("st.shared.v4.b32 [%0], {%1,%2,%3,%4};"
                         :: "r"(base + SM_AB + sw), "r"(B[0]), "r"(B[1]), "r"(B[2]), "r"(B[3]) : "memory");
            asm volatile("st.shared.v4.b32 [%0], {%1,%2,%3,%4};"
                         :: "r"(base + SM_AS + sw), "r"(S[0]), "r"(S[1]), "r"(S[2]), "r"(S[3]) : "memory");
        }
        asm volatile("cp.async.wait_group 0;" ::: "memory");
        __syncthreads();

        // ---- compute: 4 k16 steps ----
        #pragma unroll
        for (int ks = 0; ks < 4; ks++) {
            const int kk0 = ks * 16;

            uint32_t aB[2][4], aS[2][4];
            #pragma unroll
            for (int mf = 0; mf < 2; mf++) {
                uint32_t sw = SWZ((uint32_t)((m0 + mf * 16 + lrow) * 128 + (kk0 + lkb) * 2));
                ldsm4(aB[mf], base + SM_AB + sw);
                ldsm4(aS[mf], base + SM_AS + sw);
            }
            uint32_t bB[2][4], bS[2][4];
            #pragma unroll
            for (int ng = 0; ng < 2; ng++) {
                uint32_t sw = SWZ((uint32_t)((n0 + ng * 16 + lrow) * 128 + (kk0 + lkb) * 2));
                ldsm4(bB[ng], base + SM_BB + sw);
                ldsm4(bS[ng], base + SM_BS + sw);
            }
            #pragma unroll
            for (int mf = 0; mf < 2; mf++) {
                #pragma unroll
                for (int nf = 0; nf < 4; nf++) {
                    int ng = nf >> 1, sel = nf & 1;
                    mma_bf16(acc[mf][nf], aB[mf], bB[ng][sel], bB[ng][sel + 2]);
                    mma_bf16(acc[mf][nf], aB[mf], bS[ng][sel], bS[ng][sel + 2]);
                    mma_bf16(acc[mf][nf], aS[mf], bB[ng][sel], bB[ng][sel + 2]);
                }
            }
        }
    }

    // ---- epilogue: + bias, store fp32 ----
    #pragma unroll
    for (int nf = 0; nf < 4; nf++) {
        int col = n0 + nf * 8 + 2 * (lane & 3);
        float bx = __ldg(bias + col);
        float by = __ldg(bias + col + 1);
        #pragma unroll
        for (int mf = 0; mf < 2; mf++) {
            int g = row0 + m0 + mf * 16 + (lane >> 2);
            const float* a4 = acc[mf][nf];
            if (g < N_NODES) {
                float2 o = make_float2(a4[0] + bx, a4[1] + by);
                *reinterpret_cast<float2*>(out + ((size_t)t * N_NODES + g) * FEAT + col) = o;
            }
            if (g + 8 < N_NODES) {
                float2 o = make_float2(a4[2] + bx, a4[3] + by);
                *reinterpret_cast<float2*>(out + ((size_t)t * N_NODES + g + 8) * FEAT + col) = o;
            }
        }
    }
}

// ---------------------------------------------------------------------------
extern "C" void kernel_launch(void* const* d_in, const int* in_sizes, int n_in,
                              void* d_out, int out_size) {
    const float* x0     = (const float*)d_in[0];
    const float* x1     = (const float*)d_in[1];
    const float* weight = (const float*)d_in[2];
    const float* w_comp = (const float*)d_in[3];
    const float* bias   = (const float*)d_in[4];
    const int* src0 = (const int*)d_in[5];  const int* dst0 = (const int*)d_in[6];
    const int* src1 = (const int*)d_in[7];  const int* dst1 = (const int*)d_in[8];
    const int* src2 = (const int*)d_in[9];  const int* dst2 = (const int*)d_in[10];
    const int* src3 = (const int*)d_in[11]; const int* dst3 = (const int*)d_in[12];
    float* out = (float*)d_out;

    void* aptr = nullptr;
    cudaGetSymbolAddress(&aptr, g_A);
    float* A = (float*)aptr;

    cudaMemsetAsync(aptr, 0, sizeof(float) * NRELS * NF, 0);
    compute_w_kernel<<<256, 256>>>(weight, w_comp);

    int E0 = in_sizes[5], E1 = in_sizes[7], E2 = in_sizes[9], E3 = in_sizes[11];
    int Emax = E0;
    if (E1 > Emax) Emax = E1;
    if (E2 > Emax) Emax = E2;
    if (E3 > Emax) Emax = E3;
    int nblocks = ((Emax + 31) / 32) * 4;     // 32 edges per block, rel = bid & 3
    scatter4_kernel<<<nblocks, 256>>>(x0, x1, src0, dst0, src1, dst1,
                                      src2, dst2, src3, dst3, A,
                                      E0, E1, E2, E3);

    cudaFuncSetAttribute(gemm_kernel, cudaFuncAttributeMaxDynamicSharedMemorySize, SMEM_BYTES);
    gemm_kernel<<<dim3((N_NODES + 63) / 64, 2), 256, SMEM_BYTES>>>(bias, out);
}